// round 6
// baseline (speedup 1.0000x reference)
#include <cuda_runtime.h>

#define NA 100000
#define NB 100000
#define ND 50000
#define HD 128
#define OUTD 16
#define EMAX 600000

// ---------------- float arena ----------------
#define OFF_H0D   0
#define OFF_H1A   (OFF_H0D + ND * HD)
#define OFF_H1B   (OFF_H1A + NA * HD)
#define OFF_BUFA  (OFF_H1B + NB * HD)
#define OFF_BUFB  (OFF_BUFA + NA * HD)
#define OFF_INV0  (OFF_BUFB + NB * HD)
#define OFF_INV1  (OFF_INV0 + ND)
#define OFF_INV2  (OFF_INV1 + ND)
#define OFF_INV3  (OFF_INV2 + NA)
#define OFF_W00   (OFF_INV3 + NB)
#define OFF_W01   (OFF_W00 + HD * HD)
#define OFF_W12   (OFF_W01 + HD * HD)
#define OFF_W13   (OFF_W12 + HD * HD)
#define OFF_W20   (OFF_W13 + HD * HD)
#define OFF_W21   (OFF_W20 + HD * OUTD)
#define ARENA_SZ  (OFF_W21 + HD * OUTD)
__device__ float g_arena[ARENA_SZ];

// ---------------- int arena (CSR) ----------------
#define IOFF_CNT0  0
#define IOFF_CNT1  (IOFF_CNT0 + ND)
#define IOFF_CNT2  (IOFF_CNT1 + ND)
#define IOFF_CNT3  (IOFF_CNT2 + NA)
#define CNT_TOTAL  (IOFF_CNT3 + NB - IOFF_CNT0)
#define IOFF_PTR0  (IOFF_CNT3 + NB)
#define IOFF_PTR1  (IOFF_PTR0 + ND + 1)
#define IOFF_PTR2  (IOFF_PTR1 + ND + 1)
#define IOFF_PTR3  (IOFF_PTR2 + NA + 1)
#define IOFF_CUR0  (IOFF_PTR3 + NB + 1)
#define IOFF_CUR1  (IOFF_CUR0 + ND)
#define IOFF_CUR2  (IOFF_CUR1 + ND)
#define IOFF_CUR3  (IOFF_CUR2 + NA)
#define IOFF_CSR0  (IOFF_CUR3 + NB)
#define IOFF_CSR1  (IOFF_CSR0 + EMAX)
#define IOFF_CSR2  (IOFF_CSR1 + EMAX)
#define IOFF_CSR3  (IOFF_CSR2 + EMAX)
#define IARENA_SZ  (IOFF_CSR3 + EMAX)
__device__ int g_iarena[IARENA_SZ];

// ---------------- f32x2 helpers (sm_100+; IEEE fp32 per lane) ----------------
__device__ __forceinline__ unsigned long long pk2(float lo, float hi) {
    unsigned long long r;
    asm("mov.b64 %0, {%1, %2};" : "=l"(r) : "f"(lo), "f"(hi));
    return r;
}
__device__ __forceinline__ void unpk2(unsigned long long v, float& lo, float& hi) {
    asm("mov.b64 {%0, %1}, %2;" : "=f"(lo), "=f"(hi) : "l"(v));
}
__device__ __forceinline__ void fma2(unsigned long long& d, unsigned long long a, unsigned long long b) {
    asm("fma.rn.f32x2 %0, %1, %2, %0;" : "+l"(d) : "l"(a), "l"(b));
}

// ---------------- CSR build kernels (all-relations fused, proven in R4) ----------------
__global__ void zeroi_kernel(int* __restrict__ p, int n) {
    int i = blockIdx.x * blockDim.x + threadIdx.x;
    if (i < n) p[i] = 0;
}

__global__ void deg_all_kernel(const int* __restrict__ d0, int n0, const int* __restrict__ d1, int n1,
                               const int* __restrict__ d2, int n2, const int* __restrict__ d3, int n3,
                               int* __restrict__ c0, int* __restrict__ c1,
                               int* __restrict__ c2, int* __restrict__ c3) {
    int i = blockIdx.x * blockDim.x + threadIdx.x;
    if (i < n0) { atomicAdd(&c0[d0[i]], 1); return; }
    i -= n0;
    if (i < n1) { atomicAdd(&c1[d1[i]], 1); return; }
    i -= n1;
    if (i < n2) { atomicAdd(&c2[d2[i]], 1); return; }
    i -= n2;
    if (i < n3) atomicAdd(&c3[d3[i]], 1);
}

__global__ void scan4_kernel(const int* __restrict__ c0, int n0, int* p0, int* u0, float* v0,
                             const int* __restrict__ c1, int n1, int* p1, int* u1, float* v1,
                             const int* __restrict__ c2, int n2, int* p2, int* u2, float* v2,
                             const int* __restrict__ c3, int n3, int* p3, int* u3, float* v3) {
    const int* cnt; int n; int* ptr; int* cur; float* inv;
    switch (blockIdx.x) {
        case 0: cnt = c0; n = n0; ptr = p0; cur = u0; inv = v0; break;
        case 1: cnt = c1; n = n1; ptr = p1; cur = u1; inv = v1; break;
        case 2: cnt = c2; n = n2; ptr = p2; cur = u2; inv = v2; break;
        default: cnt = c3; n = n3; ptr = p3; cur = u3; inv = v3; break;
    }
    int t = threadIdx.x;
    int chunk = (n + 1023) / 1024;
    int lo = t * chunk;
    int hi = min(lo + chunk, n);
    int tot = 0;
    for (int i = lo; i < hi; i++) tot += cnt[i];
    __shared__ int ss[1024];
    ss[t] = tot;
    __syncthreads();
    for (int d = 1; d < 1024; d <<= 1) {
        int v = (t >= d) ? ss[t - d] : 0;
        __syncthreads();
        ss[t] += v;
        __syncthreads();
    }
    int off = ss[t] - tot;
    for (int i = lo; i < hi; i++) {
        int c = cnt[i];
        ptr[i] = off;
        cur[i] = off;
        inv[i] = 1.0f / (float)max(c, 1);
        off += c;
    }
    if (lo < n && hi == n) ptr[n] = off;
}

__global__ void permute_all_kernel(const int* s0, const int* d0, int n0, int* u0, int* x0,
                                   const int* s1, const int* d1, int n1, int* u1, int* x1,
                                   const int* s2, const int* d2, int n2, int* u2, int* x2,
                                   const int* s3, const int* d3, int n3, int* u3, int* x3) {
    int i = blockIdx.x * blockDim.x + threadIdx.x;
    if (i < n0) { int p = atomicAdd(&u0[d0[i]], 1); x0[p] = s0[i]; return; }
    i -= n0;
    if (i < n1) { int p = atomicAdd(&u1[d1[i]], 1); x1[p] = s1[i]; return; }
    i -= n1;
    if (i < n2) { int p = atomicAdd(&u2[d2[i]], 1); x2[p] = s2[i]; return; }
    i -= n2;
    if (i < n3) { int p = atomicAdd(&u3[d3[i]], 1); x3[p] = s3[i]; }
}

__global__ void wmix_all_kernel(const float* b0, const float* c0,
                                const float* b1, const float* c1,
                                const float* b2, const float* c2,
                                float* W00, float* W01, float* W12, float* W13,
                                float* W20, float* W21) {
    int i = blockIdx.x * blockDim.x + threadIdx.x;
    const int SZ = HD * HD, SZ2 = HD * OUTD;
    if (i < SZ)               W00[i] = c0[0] * b0[i] + c0[1] * b0[SZ + i];
    else if (i < 2 * SZ)      { int j = i - SZ;     W01[j] = c0[2] * b0[j] + c0[3] * b0[SZ + j]; }
    else if (i < 3 * SZ)      { int j = i - 2 * SZ; W12[j] = c1[4] * b1[j] + c1[5] * b1[SZ + j]; }
    else if (i < 4 * SZ)      { int j = i - 3 * SZ; W13[j] = c1[6] * b1[j] + c1[7] * b1[SZ + j]; }
    else if (i < 4 * SZ + SZ2)       { int j = i - 4 * SZ;       W20[j] = c2[0] * b2[j] + c2[1] * b2[SZ2 + j]; }
    else if (i < 4 * SZ + 2 * SZ2)   { int j = i - 4 * SZ - SZ2; W21[j] = c2[2] * b2[j] + c2[3] * b2[SZ2 + j]; }
}

// ---------------- CSR gather row body (warp-collective; lane = float4 column) ----------------
__device__ __forceinline__ void gather_row(const float4* __restrict__ feat,
                                           const int* __restrict__ csr, const int* __restrict__ ptr,
                                           const float* __restrict__ inv,
                                           float4* __restrict__ agg, int row, int lane) {
    int beg = ptr[row], end = ptr[row + 1];
    float4 acc = make_float4(0.f, 0.f, 0.f, 0.f);
    int j = beg;
    for (; j + 8 <= end; j += 8) {
        float4 v[8];
#pragma unroll
        for (int u = 0; u < 8; u++) v[u] = __ldg(&feat[csr[j + u] * 32 + lane]);
#pragma unroll
        for (int u = 0; u < 8; u++) {
            acc.x += v[u].x; acc.y += v[u].y; acc.z += v[u].z; acc.w += v[u].w;
        }
    }
    for (; j < end; j++) {
        float4 v = __ldg(&feat[csr[j] * 32 + lane]);
        acc.x += v.x; acc.y += v.y; acc.z += v.z; acc.w += v.w;
    }
    float s = inv[row];
    acc.x *= s; acc.y *= s; acc.z *= s; acc.w *= s;
    agg[row * 32 + lane] = acc;
}

// plain gather launch: one warp per row
__global__ void gather128_kernel(const float4* __restrict__ feat,
                                 const int* __restrict__ csr, const int* __restrict__ ptr,
                                 const float* __restrict__ inv,
                                 float4* __restrict__ agg, int nrows) {
    int lane = threadIdx.x & 31;
    int row = (blockIdx.x * blockDim.x + threadIdx.x) >> 5;
    if (row < nrows) gather_row(feat, csr, ptr, inv, agg, row, lane);
}

// fused r0+r1 gathers (both into d-type rows)
__global__ void gather01_kernel(const float4* __restrict__ fa,
                                const int* __restrict__ csr0, const int* __restrict__ ptr0,
                                const float* __restrict__ inv0, float4* __restrict__ agg0,
                                const float4* __restrict__ fb,
                                const int* __restrict__ csr1, const int* __restrict__ ptr1,
                                const float* __restrict__ inv1, float4* __restrict__ agg1) {
    int lane = threadIdx.x & 31;
    int w = (blockIdx.x * blockDim.x + threadIdx.x) >> 5;
    if (w < ND) gather_row(fa, csr0, ptr0, inv0, agg0, w, lane);
    else if (w < 2 * ND) gather_row(fb, csr1, ptr1, inv1, agg1, w - ND, lane);
}

// ---------------- final fused output ----------------
__global__ void gather_out_kernel(const float4* __restrict__ t1a, const float4* __restrict__ t1b,
                                  const int* __restrict__ csr0, const int* __restrict__ ptr0,
                                  const float* __restrict__ inv0,
                                  const int* __restrict__ csr1, const int* __restrict__ ptr1,
                                  const float* __restrict__ inv1,
                                  const float* __restrict__ bias, float4* __restrict__ out) {
    int t = blockIdx.x * blockDim.x + threadIdx.x;
    int row = t >> 2, q = t & 3;
    if (row >= ND) return;
    float4 a0 = make_float4(0.f, 0.f, 0.f, 0.f);
    for (int j = ptr0[row]; j < ptr0[row + 1]; j++) {
        float4 v = __ldg(&t1a[csr0[j] * 4 + q]);
        a0.x += v.x; a0.y += v.y; a0.z += v.z; a0.w += v.w;
    }
    float4 a1 = make_float4(0.f, 0.f, 0.f, 0.f);
    for (int j = ptr1[row]; j < ptr1[row + 1]; j++) {
        float4 v = __ldg(&t1b[csr1[j] * 4 + q]);
        a1.x += v.x; a1.y += v.y; a1.z += v.z; a1.w += v.w;
    }
    float i0 = inv0[row], i1 = inv1[row];
    float4 b = ((const float4*)bias)[q];
    out[row * 4 + q] = make_float4(a0.x * i0 + a1.x * i1 + b.x,
                                   a0.y * i0 + a1.y * i1 + b.y,
                                   a0.z * i0 + a1.z * i1 + b.z,
                                   a0.w * i0 + a1.w * i1 + b.w);
}

// ---------------- f32x2 GEMM bodies ----------------
__device__ __forceinline__ void mm_phase(const float4* __restrict__ As4, const float4* __restrict__ Ws4,
                                         int rg, int cx, unsigned long long (&acc2)[4][4]) {
#pragma unroll 2
    for (int k4 = 0; k4 < 32; k4++) {
        float4 a[8];
#pragma unroll
        for (int j = 0; j < 8; j++) a[j] = As4[(rg * 8 + j) * 32 + k4];
#pragma unroll
        for (int kk = 0; kk < 4; kk++) {
            float4 w = Ws4[(k4 * 4 + kk) * 32 + cx];
            unsigned long long w2x = pk2(w.x, w.x);
            unsigned long long w2y = pk2(w.y, w.y);
            unsigned long long w2z = pk2(w.z, w.z);
            unsigned long long w2w = pk2(w.w, w.w);
#pragma unroll
            for (int rp = 0; rp < 4; rp++) {
                float a0 = (kk == 0) ? a[2 * rp].x : (kk == 1) ? a[2 * rp].y
                         : (kk == 2) ? a[2 * rp].z : a[2 * rp].w;
                float a1 = (kk == 0) ? a[2 * rp + 1].x : (kk == 1) ? a[2 * rp + 1].y
                         : (kk == 2) ? a[2 * rp + 1].z : a[2 * rp + 1].w;
                unsigned long long ap = pk2(a0, a1);
                fma2(acc2[rp][0], ap, w2x);
                fma2(acc2[rp][1], ap, w2y);
                fma2(acc2[rp][2], ap, w2z);
                fma2(acc2[rp][3], ap, w2w);
            }
        }
    }
}

template <bool ACC, bool FIN, bool RELU>
__device__ __forceinline__ void mm_store(unsigned long long (&acc2)[4][4], int r0, int rg, int cx,
                                         const float* __restrict__ bias, float4* __restrict__ C4, int N) {
    float4 b4 = make_float4(0.f, 0.f, 0.f, 0.f);
    if (FIN) b4 = ((const float4*)bias)[cx];
#pragma unroll
    for (int rp = 0; rp < 4; rp++) {
        float lo[4], hi[4];
#pragma unroll
        for (int c = 0; c < 4; c++) unpk2(acc2[rp][c], lo[c], hi[c]);
#pragma unroll
        for (int half = 0; half < 2; half++) {
            int g = r0 + rg * 8 + 2 * rp + half;
            if (g >= N) continue;
            float* v = half ? hi : lo;
            float4 o = make_float4(v[0], v[1], v[2], v[3]);
            if (ACC) {
                float4 c = C4[g * 32 + cx];
                o.x += c.x; o.y += c.y; o.z += c.z; o.w += c.w;
            }
            if (FIN) {
                o.x += b4.x; o.y += b4.y; o.z += b4.z; o.w += b4.w;
                if (RELU) {
                    o.x = fmaxf(o.x, 0.f); o.y = fmaxf(o.y, 0.f);
                    o.z = fmaxf(o.z, 0.f); o.w = fmaxf(o.w, 0.f);
                }
            }
            C4[g * 32 + cx] = o;
        }
    }
}

template <bool ACC, bool FIN, bool RELU>
__device__ __forceinline__ void gemm128_body(float* sm, int blockRow,
                                             const float* __restrict__ A, const float* __restrict__ W,
                                             const float* __restrict__ bias, float* __restrict__ C, int N) {
    float4* Ws4 = (float4*)sm;
    float4* As4 = (float4*)(sm + HD * HD);
    int tid = threadIdx.x;
    int r0 = blockRow * 64;

    const float4* W4 = (const float4*)W;
    for (int i = tid; i < 4096; i += 256) Ws4[i] = W4[i];
    const float4* A4 = (const float4*)A;
    for (int i = tid; i < 2048; i += 256) {
        int g = r0 + (i >> 5);
        As4[i] = (g < N) ? A4[g * 32 + (i & 31)] : make_float4(0.f, 0.f, 0.f, 0.f);
    }
    __syncthreads();

    int cx = tid & 31, rg = tid >> 5;
    unsigned long long acc2[4][4];
#pragma unroll
    for (int rp = 0; rp < 4; rp++)
#pragma unroll
        for (int c = 0; c < 4; c++) acc2[rp][c] = 0ull;

    mm_phase(As4, Ws4, rg, cx, acc2);
    mm_store<ACC, FIN, RELU>(acc2, r0, rg, cx, bias, (float4*)C, N);
}

template <bool ACC, bool FIN, bool RELU>
__global__ void gemm128_kernel(const float* __restrict__ A, const float* __restrict__ W,
                               const float* __restrict__ bias, float* __restrict__ C, int N) {
    extern __shared__ float sm[];
    gemm128_body<ACC, FIN, RELU>(sm, blockIdx.x, A, W, bias, C, N);
}

// ---------------- fused: gemm blocks + gather blocks in one launch ----------------
// Every R-th block (indices 0, R, 2R, ... while < nGemmBlocks*R) runs the GEMM;
// all others run the 128-wide CSR gather (8 rows per block). Interleaving keeps
// fma-bound and L2-bound blocks co-resident on every SM wave.
__global__ void gemm_gather_kernel(const float* __restrict__ A, const float* __restrict__ W,
                                   const float* __restrict__ bias, float* __restrict__ C,
                                   int Ngemm, int nGemmBlocks, int R,
                                   const float4* __restrict__ feat,
                                   const int* __restrict__ csr, const int* __restrict__ ptr,
                                   const float* __restrict__ inv,
                                   float4* __restrict__ agg, int nrows) {
    extern __shared__ float sm[];
    int g = blockIdx.x / R, r = blockIdx.x % R;
    if (r == 0 && g < nGemmBlocks) {
        gemm128_body<false, true, true>(sm, g, A, W, bias, C, Ngemm);
    } else {
        int nBefore = min(g + (r ? 1 : 0), nGemmBlocks);
        int gb = blockIdx.x - nBefore;
        int lane = threadIdx.x & 31;
        int row = gb * 8 + (threadIdx.x >> 5);
        if (row < nrows) gather_row(feat, csr, ptr, inv, agg, row, lane);
    }
}

// C[N,16] = A[N,128] @ W[128,16] (pure transform). 128 thr, row per thread.
__global__ void gemm16_kernel(const float* __restrict__ A, const float* __restrict__ W,
                              float* __restrict__ C, int N) {
    extern __shared__ float sm[];
    float* Ws = sm;
    float* As = sm + HD * OUTD;
    int tid = threadIdx.x;
    int r0 = blockIdx.x * 128;

    for (int i = tid; i < HD * OUTD; i += 128) Ws[i] = W[i];
    const float4* A4 = (const float4*)A;
    for (int i = tid; i < 128 * 32; i += 128) {
        int row = i >> 5, c4 = i & 31;
        int g = r0 + row;
        float4 v = (g < N) ? A4[g * 32 + c4] : make_float4(0.f, 0.f, 0.f, 0.f);
        float* p = &As[row * 129 + c4 * 4];
        p[0] = v.x; p[1] = v.y; p[2] = v.z; p[3] = v.w;
    }
    __syncthreads();

    float acc[16];
#pragma unroll
    for (int c = 0; c < 16; c++) acc[c] = 0.f;
    const float* arow = &As[tid * 129];
#pragma unroll 4
    for (int k = 0; k < HD; k++) {
        float a = arow[k];
        const float4* wr = (const float4*)&Ws[k * 16];
#pragma unroll
        for (int q = 0; q < 4; q++) {
            float4 w = wr[q];
            acc[q * 4 + 0] += a * w.x;
            acc[q * 4 + 1] += a * w.y;
            acc[q * 4 + 2] += a * w.z;
            acc[q * 4 + 3] += a * w.w;
        }
    }
    int g = r0 + tid;
    if (g < N) {
        float4* C4 = (float4*)C;
#pragma unroll
        for (int q = 0; q < 4; q++)
            C4[g * 4 + q] = make_float4(acc[q * 4], acc[q * 4 + 1], acc[q * 4 + 2], acc[q * 4 + 3]);
    }
}

// ---------------- host launcher (single stream, no stream/event APIs) ----------------
static const int SMEM128 = (HD * HD + 64 * HD) * (int)sizeof(float);      // 96 KB
static const int SMEM16  = (HD * OUTD + 128 * 129) * (int)sizeof(float);  // ~72.5 KB

extern "C" void kernel_launch(void* const* d_in, const int* in_sizes, int n_in,
                              void* d_out, int out_size) {
    const float* feat_a = (const float*)d_in[0];
    const float* feat_b = (const float*)d_in[1];
    // feat_d (d_in[2]) is provably unused by the returned output.
    const float* basis0 = (const float*)d_in[3];
    const float* coef0  = (const float*)d_in[4];
    const float* bias0  = (const float*)d_in[5];
    const float* basis1 = (const float*)d_in[6];
    const float* coef1  = (const float*)d_in[7];
    const float* bias1  = (const float*)d_in[8];
    const float* basis2 = (const float*)d_in[9];
    const float* coef2  = (const float*)d_in[10];
    const float* bias2  = (const float*)d_in[11];
    const int* e0s = (const int*)d_in[12]; const int* e0d = (const int*)d_in[13];
    const int* e1s = (const int*)d_in[14]; const int* e1d = (const int*)d_in[15];
    const int* e2s = (const int*)d_in[16]; const int* e2d = (const int*)d_in[17];
    const int* e3s = (const int*)d_in[18]; const int* e3d = (const int*)d_in[19];
    int ne0 = in_sizes[12], ne1 = in_sizes[14], ne2 = in_sizes[16], ne3 = in_sizes[18];
    float* out = (float*)d_out;

    float* arena = nullptr;
    cudaGetSymbolAddress((void**)&arena, g_arena);
    int* ia = nullptr;
    cudaGetSymbolAddress((void**)&ia, g_iarena);

    float* h0d  = arena + OFF_H0D;
    float* h1a  = arena + OFF_H1A;
    float* h1b  = arena + OFF_H1B;
    float* bufA = arena + OFF_BUFA;
    float* bufB = arena + OFF_BUFB;
    float* aggd0 = bufA;                 // ND*HD fits while bufA dead
    float* aggd1 = bufB;
    float* t1a  = bufA;                  // NA*16 (after fused gemm consumes bufA)
    float* t1b  = bufB;                  // NB*16
    float* inv0 = arena + OFF_INV0;
    float* inv1 = arena + OFF_INV1;
    float* inv2 = arena + OFF_INV2;
    float* inv3 = arena + OFF_INV3;
    float* W00 = arena + OFF_W00;
    float* W01 = arena + OFF_W01;
    float* W12 = arena + OFF_W12;
    float* W13 = arena + OFF_W13;
    float* W20 = arena + OFF_W20;
    float* W21 = arena + OFF_W21;

    int* cnt0 = ia + IOFF_CNT0; int* cnt1 = ia + IOFF_CNT1;
    int* cnt2 = ia + IOFF_CNT2; int* cnt3 = ia + IOFF_CNT3;
    int* ptr0 = ia + IOFF_PTR0; int* ptr1 = ia + IOFF_PTR1;
    int* ptr2 = ia + IOFF_PTR2; int* ptr3 = ia + IOFF_PTR3;
    int* cur0 = ia + IOFF_CUR0; int* cur1 = ia + IOFF_CUR1;
    int* cur2 = ia + IOFF_CUR2; int* cur3 = ia + IOFF_CUR3;
    int* csr0 = ia + IOFF_CSR0; int* csr1 = ia + IOFF_CSR1;
    int* csr2 = ia + IOFF_CSR2; int* csr3 = ia + IOFF_CSR3;

    cudaFuncSetAttribute(gemm128_kernel<false, false, false>, cudaFuncAttributeMaxDynamicSharedMemorySize, SMEM128);
    cudaFuncSetAttribute(gemm128_kernel<true, true, true>,    cudaFuncAttributeMaxDynamicSharedMemorySize, SMEM128);
    cudaFuncSetAttribute(gemm128_kernel<false, true, true>,   cudaFuncAttributeMaxDynamicSharedMemorySize, SMEM128);
    cudaFuncSetAttribute(gemm_gather_kernel,                  cudaFuncAttributeMaxDynamicSharedMemorySize, SMEM128);
    cudaFuncSetAttribute(gemm16_kernel,                       cudaFuncAttributeMaxDynamicSharedMemorySize, SMEM16);

    const int T = 256;
    int neall = ne0 + ne1 + ne2 + ne3;

    // 0-4: CSR build + weights
    zeroi_kernel<<<(CNT_TOTAL + T - 1) / T, T>>>(cnt0, CNT_TOTAL);
    deg_all_kernel<<<(neall + T - 1) / T, T>>>(e0d, ne0, e1d, ne1, e2d, ne2, e3d, ne3,
                                               cnt0, cnt1, cnt2, cnt3);
    scan4_kernel<<<4, 1024>>>(cnt0, ND, ptr0, cur0, inv0,
                              cnt1, ND, ptr1, cur1, inv1,
                              cnt2, NA, ptr2, cur2, inv2,
                              cnt3, NB, ptr3, cur3, inv3);
    permute_all_kernel<<<(neall + T - 1) / T, T>>>(e0s, e0d, ne0, cur0, csr0,
                                                   e1s, e1d, ne1, cur1, csr1,
                                                   e2s, e2d, ne2, cur2, csr2,
                                                   e3s, e3d, ne3, cur3, csr3);
    wmix_all_kernel<<<(4 * HD * HD + 2 * HD * OUTD + T - 1) / T, T>>>(
        basis0, coef0, basis1, coef1, basis2, coef2, W00, W01, W12, W13, W20, W21);

    // 5: fused layer-0 gathers (r0 -> aggd0, r1 -> aggd1)
    gather01_kernel<<<(2 * ND * 32 + T - 1) / T, T>>>(
        (const float4*)feat_a, csr0, ptr0, inv0, (float4*)aggd0,
        (const float4*)feat_b, csr1, ptr1, inv1, (float4*)aggd1);

    // 6-7: layer 0 GEMMs (plain then accumulate+bias+relu); 96KB smem = 2 blocks/SM
    gemm128_kernel<false, false, false><<<(ND + 63) / 64, 256, SMEM128>>>(aggd0, W00, nullptr, h0d, ND);
    gemm128_kernel<true, true, true><<<(ND + 63) / 64, 256, SMEM128>>>(aggd1, W01, bias0, h0d, ND);

    // 8: gather r2 (h0d -> bufA)
    gather128_kernel<<<(NA * 32 + T - 1) / T, T>>>((const float4*)h0d, csr2, ptr2, inv2, (float4*)bufA, NA);

    // 9: FUSED — gemm h1a (fma-bound) overlapped with gather r3 (L2-bound)
    {
        int nGemm = (NA + 63) / 64;                 // 1563
        int nGath = (NB + 7) / 8;                   // 12500
        int total = nGemm + nGath;
        int R = total / nGemm;                       // ~9 -> gemm blocks spread through grid
        if (R < 1) R = 1;
        gemm_gather_kernel<<<total, 256, SMEM128>>>(bufA, W12, bias1, h1a, NA, nGemm, R,
                                                    (const float4*)h0d, csr3, ptr3, inv3,
                                                    (float4*)bufB, NB);
    }

    // 10: gemm h1b
    gemm128_kernel<false, true, true><<<(NB + 63) / 64, 256, SMEM128>>>(bufB, W13, bias1, h1b, NB);

    // 11-12: layer-2 projections (transform-first)
    gemm16_kernel<<<(NA + 127) / 128, 128, SMEM16>>>(h1a, W20, t1a, NA);
    gemm16_kernel<<<(NB + 127) / 128, 128, SMEM16>>>(h1b, W21, t1b, NB);

    // 13: fused 16-wide double gather + normalize + bias into d_out
    gather_out_kernel<<<(ND * 4 + T - 1) / T, T>>>((const float4*)t1a, (const float4*)t1b,
                                                   csr0, ptr0, inv0, csr1, ptr1, inv1,
                                                   bias2, (float4*)out);
}

// round 12
// speedup vs baseline: 1.0789x; 1.0789x over previous
#include <cuda_runtime.h>

#define NA 100000
#define NB 100000
#define ND 50000
#define HD 128
#define OUTD 16

// ---------------- device scratch: one flat arena ----------------
#define OFF_H0D   0
#define OFF_H1A   (OFF_H0D + ND * HD)
#define OFF_H1B   (OFF_H1A + NA * HD)
#define OFF_BUFA  (OFF_H1B + NB * HD)
#define OFF_BUFB  (OFF_BUFA + NA * HD)
#define OFF_INV0  (OFF_BUFB + NB * HD)
#define OFF_INV1  (OFF_INV0 + ND)
#define OFF_INV2  (OFF_INV1 + ND)
#define OFF_INV3  (OFF_INV2 + NA)
#define OFF_W00   (OFF_INV3 + NB)
#define OFF_W01   (OFF_W00 + HD * HD)
#define OFF_W12   (OFF_W01 + HD * HD)
#define OFF_W13   (OFF_W12 + HD * HD)
#define OFF_W20   (OFF_W13 + HD * HD)
#define OFF_W21   (OFF_W20 + HD * OUTD)
#define ARENA_SZ  (OFF_W21 + HD * OUTD)

__device__ float g_arena[ARENA_SZ];

// ---------------- f32x2 helpers (sm_100+; IEEE fp32 per lane) ----------------
__device__ __forceinline__ unsigned long long pk2(float lo, float hi) {
    unsigned long long r;
    asm("mov.b64 %0, {%1, %2};" : "=l"(r) : "f"(lo), "f"(hi));
    return r;
}
__device__ __forceinline__ void unpk2(unsigned long long v, float& lo, float& hi) {
    asm("mov.b64 {%0, %1}, %2;" : "=f"(lo), "=f"(hi) : "l"(v));
}
__device__ __forceinline__ void fma2(unsigned long long& d, unsigned long long a, unsigned long long b) {
    asm("fma.rn.f32x2 %0, %1, %2, %0;" : "+l"(d) : "l"(a), "l"(b));
}

// ---------------- small utility kernels ----------------
__global__ void zero4_kernel(float4* __restrict__ p, int n4) {
    int i = blockIdx.x * blockDim.x + threadIdx.x;
    if (i < n4) p[i] = make_float4(0.f, 0.f, 0.f, 0.f);
}

__global__ void deg_kernel(const int* __restrict__ dst, int ne, float* __restrict__ deg) {
    int i = blockIdx.x * blockDim.x + threadIdx.x;
    if (i < ne) atomicAdd(&deg[dst[i]], 1.0f);
}

__global__ void inv_kernel(float* __restrict__ d, int n) {
    int i = blockIdx.x * blockDim.x + threadIdx.x;
    if (i < n) d[i] = 1.0f / fmaxf(d[i], 1.0f);
}

// W[r] = coef[r,0]*basis[0] + coef[r,1]*basis[1]   (NUM_BASES = 2)
__global__ void wmix_kernel(const float* __restrict__ basis, const float* __restrict__ coef,
                            int r, int sz, float* __restrict__ W) {
    int i = blockIdx.x * blockDim.x + threadIdx.x;
    if (i < sz) W[i] = coef[2 * r] * basis[i] + coef[2 * r + 1] * basis[sz + i];
}

// ---------------- edge scatter: agg[dst] += feat[src], 128 floats/row ----------------
__global__ void scatter128_kernel(const float4* __restrict__ feat,
                                  const int* __restrict__ esrc, const int* __restrict__ edst,
                                  float4* __restrict__ agg, int ne) {
    int lane = threadIdx.x & 31;
    int e = (blockIdx.x * blockDim.x + threadIdx.x) >> 5;
    if (e >= ne) return;
    int s = esrc[e];
    int d = edst[e];
    float4 v = feat[s * 32 + lane];
    float4* p = agg + d * 32 + lane;
    asm volatile("red.global.add.v4.f32 [%0], {%1,%2,%3,%4};"
                 :: "l"(p), "f"(v.x), "f"(v.y), "f"(v.z), "f"(v.w)
                 : "memory");
}

// ---------------- edge scatter, 16 floats/row: 4 lanes per edge ----------------
__global__ void scatter16_kernel(const float4* __restrict__ feat,
                                 const int* __restrict__ esrc, const int* __restrict__ edst,
                                 float4* __restrict__ agg, int ne) {
    int t = blockIdx.x * blockDim.x + threadIdx.x;
    int e = t >> 2;
    int q = t & 3;
    if (e >= ne) return;
    int s = esrc[e];
    int d = edst[e];
    float4 v = feat[s * 4 + q];
    float4* p = agg + d * 4 + q;
    asm volatile("red.global.add.v4.f32 [%0], {%1,%2,%3,%4};"
                 :: "l"(p), "f"(v.x), "f"(v.y), "f"(v.z), "f"(v.w)
                 : "memory");
}

// out[r,:] = a0[r,:]*inv0[r] + a1[r,:]*inv1[r] + bias  (16-wide rows)
__global__ void combine16_kernel(const float* __restrict__ a0, const float* __restrict__ a1,
                                 const float* __restrict__ inv0, const float* __restrict__ inv1,
                                 const float* __restrict__ bias, float* __restrict__ out, int n) {
    int i = blockIdx.x * blockDim.x + threadIdx.x;
    if (i < n) {
        int r = i >> 4;
        out[i] = a0[i] * inv0[r] + a1[i] * inv1[r] + bias[i & 15];
    }
}

// ---------------- f32x2 GEMM mainloop: acc += (As tile) @ (Ws tile) ----------------
__device__ __forceinline__ void mm_phase(const float4* __restrict__ As4, const float4* __restrict__ Ws4,
                                         int rg, int cx, unsigned long long (&acc2)[4][4]) {
#pragma unroll 2
    for (int k4 = 0; k4 < 32; k4++) {
        float4 a[8];
#pragma unroll
        for (int j = 0; j < 8; j++) a[j] = As4[(rg * 8 + j) * 32 + k4];
#pragma unroll
        for (int kk = 0; kk < 4; kk++) {
            float4 w = Ws4[(k4 * 4 + kk) * 32 + cx];
            unsigned long long w2x = pk2(w.x, w.x);
            unsigned long long w2y = pk2(w.y, w.y);
            unsigned long long w2z = pk2(w.z, w.z);
            unsigned long long w2w = pk2(w.w, w.w);
#pragma unroll
            for (int rp = 0; rp < 4; rp++) {
                float a0 = (kk == 0) ? a[2 * rp].x : (kk == 1) ? a[2 * rp].y
                         : (kk == 2) ? a[2 * rp].z : a[2 * rp].w;
                float a1 = (kk == 0) ? a[2 * rp + 1].x : (kk == 1) ? a[2 * rp + 1].y
                         : (kk == 2) ? a[2 * rp + 1].z : a[2 * rp + 1].w;
                unsigned long long ap = pk2(a0, a1);
                fma2(acc2[rp][0], ap, w2x);
                fma2(acc2[rp][1], ap, w2y);
                fma2(acc2[rp][2], ap, w2z);
                fma2(acc2[rp][3], ap, w2w);
            }
        }
    }
}

__device__ __forceinline__ void load_tiles(float* sm, const float* __restrict__ A,
                                           const float* __restrict__ inv,
                                           const float* __restrict__ W, int r0, int N, int tid) {
    const float4* W4 = (const float4*)W;
    float4* Ws4 = (float4*)sm;
    for (int i = tid; i < HD * HD / 4; i += 256) Ws4[i] = W4[i];
    const float4* A4 = (const float4*)A;
    float4* As4 = (float4*)(sm + HD * HD);
    for (int i = tid; i < 64 * 32; i += 256) {
        int row = i >> 5;
        int g = r0 + row;
        float4 v = make_float4(0.f, 0.f, 0.f, 0.f);
        if (g < N) {
            v = A4[g * 32 + (i & 31)];
            float s = inv[g];
            v.x *= s; v.y *= s; v.z *= s; v.w *= s;
        }
        As4[i] = v;
    }
}

__device__ __forceinline__ void mm_store_final(unsigned long long (&acc2)[4][4], int r0, int rg, int cx,
                                               const float* __restrict__ bias, bool relu,
                                               float4* __restrict__ C4, int N) {
    float4 b4 = ((const float4*)bias)[cx];
#pragma unroll
    for (int rp = 0; rp < 4; rp++) {
        float lo[4], hi[4];
#pragma unroll
        for (int c = 0; c < 4; c++) unpk2(acc2[rp][c], lo[c], hi[c]);
#pragma unroll
        for (int half = 0; half < 2; half++) {
            int g = r0 + rg * 8 + 2 * rp + half;
            if (g >= N) continue;
            float* v = half ? hi : lo;
            float4 o = make_float4(v[0] + b4.x, v[1] + b4.y, v[2] + b4.z, v[3] + b4.w);
            if (relu) {
                o.x = fmaxf(o.x, 0.f); o.y = fmaxf(o.y, 0.f);
                o.z = fmaxf(o.z, 0.f); o.w = fmaxf(o.w, 0.f);
            }
            C4[g * 32 + cx] = o;
        }
    }
}

// C[N,128] = relu((A*inv)@W + bias). 256 thr, 64-row tile, 96KB smem (2 blocks/SM).
__global__ void gemm128_kernel(const float* __restrict__ A, const float* __restrict__ inv,
                               const float* __restrict__ W, const float* __restrict__ bias,
                               float* __restrict__ C, int N) {
    extern __shared__ float sm[];
    int tid = threadIdx.x;
    int r0 = blockIdx.x * 64;

    load_tiles(sm, A, inv, W, r0, N, tid);
    __syncthreads();

    int cx = tid & 31, rg = tid >> 5;
    unsigned long long acc2[4][4];
#pragma unroll
    for (int rp = 0; rp < 4; rp++)
#pragma unroll
        for (int c = 0; c < 4; c++) acc2[rp][c] = 0ull;

    mm_phase((const float4*)(sm + HD * HD), (const float4*)sm, rg, cx, acc2);
    mm_store_final(acc2, r0, rg, cx, bias, true, (float4*)C, N);
}

// C[N,128] = relu((A0*inv0)@W0 + (A1*inv1)@W1 + bias). Sequential two-phase at the
// SAME 96KB footprint (2 blocks/SM): accumulators persist in registers while smem
// is refilled with the second relation's tiles. Removes the h0d RMW pass.
__global__ void gemm128_dual_kernel(const float* __restrict__ A0, const float* __restrict__ inv0,
                                    const float* __restrict__ W0,
                                    const float* __restrict__ A1, const float* __restrict__ inv1,
                                    const float* __restrict__ W1,
                                    const float* __restrict__ bias, float* __restrict__ C, int N) {
    extern __shared__ float sm[];
    int tid = threadIdx.x;
    int r0 = blockIdx.x * 64;
    int cx = tid & 31, rg = tid >> 5;

    unsigned long long acc2[4][4];
#pragma unroll
    for (int rp = 0; rp < 4; rp++)
#pragma unroll
        for (int c = 0; c < 4; c++) acc2[rp][c] = 0ull;

    load_tiles(sm, A0, inv0, W0, r0, N, tid);
    __syncthreads();
    mm_phase((const float4*)(sm + HD * HD), (const float4*)sm, rg, cx, acc2);
    __syncthreads();                                   // all reads done before refill

    load_tiles(sm, A1, inv1, W1, r0, N, tid);
    __syncthreads();
    mm_phase((const float4*)(sm + HD * HD), (const float4*)sm, rg, cx, acc2);

    mm_store_final(acc2, r0, rg, cx, bias, true, (float4*)C, N);
}

// ---------------- GEMM: C[N,16] = A[N,128] @ W[128,16] (pure transform) ----------------
__global__ void gemm16_kernel(const float* __restrict__ A, const float* __restrict__ W,
                              float* __restrict__ C, int N) {
    extern __shared__ float sm[];
    float* Ws = sm;                 // 128*16
    float* As = sm + HD * OUTD;     // 128 * 129
    int tid = threadIdx.x;          // 128
    int r0 = blockIdx.x * 128;

    for (int i = tid; i < HD * OUTD; i += 128) Ws[i] = W[i];

    const float4* A4 = (const float4*)A;
    for (int i = tid; i < 128 * 32; i += 128) {
        int row = i >> 5, c4 = i & 31;
        int g = r0 + row;
        float4 v = make_float4(0.f, 0.f, 0.f, 0.f);
        if (g < N) v = A4[g * 32 + c4];
        float* p = &As[row * 129 + c4 * 4];
        p[0] = v.x; p[1] = v.y; p[2] = v.z; p[3] = v.w;
    }
    __syncthreads();

    float acc[16];
#pragma unroll
    for (int c = 0; c < 16; c++) acc[c] = 0.f;
    const float* arow = &As[tid * 129];
#pragma unroll 4
    for (int k = 0; k < HD; k++) {
        float a = arow[k];
        const float4* wr = (const float4*)&Ws[k * 16];
#pragma unroll
        for (int q = 0; q < 4; q++) {
            float4 w = wr[q];
            acc[q * 4 + 0] += a * w.x;
            acc[q * 4 + 1] += a * w.y;
            acc[q * 4 + 2] += a * w.z;
            acc[q * 4 + 3] += a * w.w;
        }
    }

    int g = r0 + tid;
    if (g < N) {
        float4* C4 = (float4*)C;
#pragma unroll
        for (int q = 0; q < 4; q++)
            C4[g * 4 + q] = make_float4(acc[q * 4], acc[q * 4 + 1], acc[q * 4 + 2], acc[q * 4 + 3]);
    }
}

// ---------------- host launcher ----------------
static const int SMEM128 = (HD * HD + 64 * HD) * (int)sizeof(float);        // 96 KB
static const int SMEM16  = (HD * OUTD + 128 * 129) * (int)sizeof(float);    // ~72.5 KB

extern "C" void kernel_launch(void* const* d_in, const int* in_sizes, int n_in,
                              void* d_out, int out_size) {
    const float* feat_a = (const float*)d_in[0];
    const float* feat_b = (const float*)d_in[1];
    // feat_d (d_in[2]) is provably unused by the returned output.
    const float* basis0 = (const float*)d_in[3];
    const float* coef0  = (const float*)d_in[4];
    const float* bias0  = (const float*)d_in[5];
    const float* basis1 = (const float*)d_in[6];
    const float* coef1  = (const float*)d_in[7];
    const float* bias1  = (const float*)d_in[8];
    const float* basis2 = (const float*)d_in[9];
    const float* coef2  = (const float*)d_in[10];
    const float* bias2  = (const float*)d_in[11];
    const int* e0s = (const int*)d_in[12]; const int* e0d = (const int*)d_in[13];
    const int* e1s = (const int*)d_in[14]; const int* e1d = (const int*)d_in[15];
    const int* e2s = (const int*)d_in[16]; const int* e2d = (const int*)d_in[17];
    const int* e3s = (const int*)d_in[18]; const int* e3d = (const int*)d_in[19];
    int ne0 = in_sizes[12], ne1 = in_sizes[14], ne2 = in_sizes[16], ne3 = in_sizes[18];
    float* out = (float*)d_out;

    float* arena = nullptr;
    cudaGetSymbolAddress((void**)&arena, g_arena);
    float* h0d  = arena + OFF_H0D;
    float* h1a  = arena + OFF_H1A;
    float* h1b  = arena + OFF_H1B;
    float* bufA = arena + OFF_BUFA;
    float* bufB = arena + OFF_BUFB;
    float* aggd0 = bufA;              // ND*HD fits while bufA dead
    float* aggd1 = bufB;
    float* t1a  = bufA;                       // NA*16
    float* g16_0 = bufA + NA * OUTD;          // ND*16
    float* t1b  = bufB;                       // NB*16
    float* g16_1 = bufB + NB * OUTD;          // ND*16
    float* inv0 = arena + OFF_INV0;
    float* inv1 = arena + OFF_INV1;
    float* inv2 = arena + OFF_INV2;
    float* inv3 = arena + OFF_INV3;
    float* W00 = arena + OFF_W00;
    float* W01 = arena + OFF_W01;
    float* W12 = arena + OFF_W12;
    float* W13 = arena + OFF_W13;
    float* W20 = arena + OFF_W20;
    float* W21 = arena + OFF_W21;

    cudaFuncSetAttribute(gemm128_kernel,      cudaFuncAttributeMaxDynamicSharedMemorySize, SMEM128);
    cudaFuncSetAttribute(gemm128_dual_kernel, cudaFuncAttributeMaxDynamicSharedMemorySize, SMEM128);
    cudaFuncSetAttribute(gemm16_kernel,       cudaFuncAttributeMaxDynamicSharedMemorySize, SMEM16);

    const int T = 256;

    // ---- heavy scatters early (ncu skip lands on real work) ----
    zero4_kernel<<<(ND / 4 + T - 1) / T, T>>>((float4*)inv0, ND / 4);
    zero4_kernel<<<(ND / 4 + T - 1) / T, T>>>((float4*)inv1, ND / 4);
    zero4_kernel<<<(NA / 4 + T - 1) / T, T>>>((float4*)inv2, NA / 4);
    zero4_kernel<<<(NB / 4 + T - 1) / T, T>>>((float4*)inv3, NB / 4);
    zero4_kernel<<<(ND * 32 + T - 1) / T, T>>>((float4*)aggd0, ND * 32);
    scatter128_kernel<<<(ne0 * 32 + T - 1) / T, T>>>((const float4*)feat_a, e0s, e0d, (float4*)aggd0, ne0);
    zero4_kernel<<<(ND * 32 + T - 1) / T, T>>>((float4*)aggd1, ND * 32);
    scatter128_kernel<<<(ne1 * 32 + T - 1) / T, T>>>((const float4*)feat_b, e1s, e1d, (float4*)aggd1, ne1);

    deg_kernel<<<(ne0 + T - 1) / T, T>>>(e0d, ne0, inv0);
    deg_kernel<<<(ne1 + T - 1) / T, T>>>(e1d, ne1, inv1);
    deg_kernel<<<(ne2 + T - 1) / T, T>>>(e2d, ne2, inv2);
    deg_kernel<<<(ne3 + T - 1) / T, T>>>(e3d, ne3, inv3);
    inv_kernel<<<(ND + T - 1) / T, T>>>(inv0, ND);
    inv_kernel<<<(ND + T - 1) / T, T>>>(inv1, ND);
    inv_kernel<<<(NA + T - 1) / T, T>>>(inv2, NA);
    inv_kernel<<<(NB + T - 1) / T, T>>>(inv3, NB);

    wmix_kernel<<<(HD * HD + T - 1) / T, T>>>(basis0, coef0, 0, HD * HD, W00);
    wmix_kernel<<<(HD * HD + T - 1) / T, T>>>(basis0, coef0, 1, HD * HD, W01);
    wmix_kernel<<<(HD * HD + T - 1) / T, T>>>(basis1, coef1, 2, HD * HD, W12);
    wmix_kernel<<<(HD * HD + T - 1) / T, T>>>(basis1, coef1, 3, HD * HD, W13);
    wmix_kernel<<<(HD * OUTD + T - 1) / T, T>>>(basis2, coef2, 0, HD * OUTD, W20);
    wmix_kernel<<<(HD * OUTD + T - 1) / T, T>>>(basis2, coef2, 1, HD * OUTD, W21);

    // ---- Layer 0: single dual-phase GEMM (no RMW pass over h0d) ----
    gemm128_dual_kernel<<<(ND + 63) / 64, 256, SMEM128>>>(aggd0, inv0, W00,
                                                          aggd1, inv1, W01, bias0, h0d, ND);

    // ---- Layer 1 ----
    zero4_kernel<<<(NA * 32 + T - 1) / T, T>>>((float4*)bufA, NA * 32);
    zero4_kernel<<<(NB * 32 + T - 1) / T, T>>>((float4*)bufB, NB * 32);
    scatter128_kernel<<<(ne2 * 32 + T - 1) / T, T>>>((const float4*)h0d, e2s, e2d, (float4*)bufA, ne2);
    scatter128_kernel<<<(ne3 * 32 + T - 1) / T, T>>>((const float4*)h0d, e3s, e3d, (float4*)bufB, ne3);
    gemm128_kernel<<<(NA + 63) / 64, 256, SMEM128>>>(bufA, inv2, W12, bias1, h1a, NA);
    gemm128_kernel<<<(NB + 63) / 64, 256, SMEM128>>>(bufB, inv3, W13, bias1, h1b, NB);

    // ---- Layer 2 (transform-first): t1 = h1 @ W2x, 16-wide scatter, combine ----
    gemm16_kernel<<<(NA + 127) / 128, 128, SMEM16>>>(h1a, W20, t1a, NA);
    gemm16_kernel<<<(NB + 127) / 128, 128, SMEM16>>>(h1b, W21, t1b, NB);
    zero4_kernel<<<(ND * 4 + T - 1) / T, T>>>((float4*)g16_0, ND * 4);
    zero4_kernel<<<(ND * 4 + T - 1) / T, T>>>((float4*)g16_1, ND * 4);
    scatter16_kernel<<<(ne0 * 4 + T - 1) / T, T>>>((const float4*)t1a, e0s, e0d, (float4*)g16_0, ne0);
    scatter16_kernel<<<(ne1 * 4 + T - 1) / T, T>>>((const float4*)t1b, e1s, e1d, (float4*)g16_1, ne1);
    combine16_kernel<<<(ND * OUTD + T - 1) / T, T>>>(g16_0, g16_1, inv0, inv1, bias2, out, ND * OUTD);
}